// round 4
// baseline (speedup 1.0000x reference)
#include <cuda_runtime.h>

#define BATCH   65536
#define NPLAYER 3
#define OBSD    48
#define TB      32
#define THREADS 512

// pitches (floats) — all conflict-free for their fragment patterns
#define PHID 388
#define PENC 580
#define PH1  260
#define PWB  264
#define PW1B 584
#define PSCR 260

// smem float offsets
#define HID_OFF 0                       // 12416: hid(388) -> stage2 scratch(260) -> h2(256)
#define ENC_OFF 12416                   // 18560: obs(48) -> enc(580) -> stage3 scratch(260) | w3 stash @ +8400
#define H1_OFF  (ENC_OFF + 18560)       // 8320:  h1(260)
#define WB_OFF  (H1_OFF + 8320)         // 18688: 1b weights (2x16x584) / pi ring (4x16x264)
#define SMEM_FLOATS (WB_OFF + 18688)    // 57984 floats = 231936 B
#define W3_STASH (ENC_OFF + 8400)

__device__ __forceinline__ float lrelu(float x) { return fmaxf(x, 0.01f * x); }

__device__ __forceinline__ unsigned f2tf(float x) {
    unsigned r;
    asm("cvt.rna.tf32.f32 %0, %1;" : "=r"(r) : "f"(x));
    return r;
}
__device__ __forceinline__ float tf32f(float x) { return __uint_as_float(f2tf(x)); }

__device__ __forceinline__ void mma_tf32(float d[4], unsigned a0, unsigned a1,
                                         unsigned a2, unsigned a3,
                                         unsigned b0, unsigned b1) {
    asm volatile(
        "mma.sync.aligned.m16n8k8.row.col.f32.tf32.tf32.f32 "
        "{%0,%1,%2,%3}, {%4,%5,%6,%7}, {%8,%9}, {%0,%1,%2,%3};"
        : "+f"(d[0]), "+f"(d[1]), "+f"(d[2]), "+f"(d[3])
        : "r"(a0), "r"(a1), "r"(a2), "r"(a3), "r"(b0), "r"(b1));
}

__device__ __forceinline__ unsigned cvta_s(const void* p) {
    return (unsigned)__cvta_generic_to_shared(p);
}
__device__ __forceinline__ void cpa16(unsigned dst, const void* src) {
    asm volatile("cp.async.ca.shared.global [%0], [%1], 16;" :: "r"(dst), "l"(src));
}
#define CP_COMMIT() asm volatile("cp.async.commit_group;")
template<int N> __device__ __forceinline__ void cp_wait() {
    asm volatile("cp.async.wait_group %0;" :: "n"(N));
}

// ---- stage 1b weight chunk staging: 16 k-rows x 576 cols -> buf (pitch PW1B) ----
template<int HC, int NH>
__device__ __forceinline__ void stage_1b(const float* __restrict__ W, float* dst,
                                         int p, int k0, int tid) {
    for (int g = tid; g < 2304; g += THREADS) {
        int k = g / 144;
        int c = (g - k * 144) * 4;
        int head = (HC == 576) ? 0 : ((HC == 64) ? (c >> 6) : (c >= 288 ? 1 : 0));
        int cc = c - head * HC;
        cpa16(cvta_s(dst + k * PW1B + c),
              W + ((size_t)(p * NH + head) * 32 + k0 + k) * HC + cc);
    }
}

// ---- pi weight chunk staging: both halves' chunk c (16 x 256 each) ----
__device__ __forceinline__ void stage_pi(const float* __restrict__ W0, float* wb,
                                         int KHALF, int c, int tid) {
    #pragma unroll
    for (int q = 0; q < 4; q++) {
        int g = q * THREADS + tid;          // 0..2047
        int half = g >> 10, g2 = g & 1023, k = g2 >> 6, c4 = g2 & 63;
        cpa16(cvta_s(wb + (half * 2 + (c & 1)) * (16 * PWB) + k * PWB + c4 * 4),
              W0 + ((size_t)(half * KHALF + c * 16 + k)) * 256 + c4 * 4);
    }
}

// ---- stage-1b mma / epilogue (12 mma warps x 6 n8-tiles) ----
template<int HC, int NH, int ABASE>
__device__ __forceinline__ void enc_mma(const float* s_hid, const float* wbuf,
                                        int warp, int lane, int kh,
                                        float acc[6][2][4]) {
    if (warp >= 12) return;
    const int gr = lane >> 2, gc = lane & 3;
    const int cw = warp * 48;
    #pragma unroll
    for (int ks = 0; ks < 2; ks++) {
        const int kg = kh * 16 + ks * 8;
        const int kl = ks * 8;
        int cur = -1;
        unsigned a[2][4];
        #pragma unroll
        for (int t = 0; t < 6; t++) {
            int c0 = cw + t * 8;
            int head = (HC == 576) ? 0 : ((HC == 64) ? (c0 >> 6) : (c0 >= 288 ? 1 : 0));
            if (head != cur) {
                cur = head;
                int ac = ABASE + head * 32 + kg;
                #pragma unroll
                for (int m = 0; m < 2; m++) {
                    int r = m * 16 + gr;
                    a[m][0] = __float_as_uint(s_hid[(r    ) * PHID + ac + gc    ]);
                    a[m][1] = __float_as_uint(s_hid[(r + 8) * PHID + ac + gc    ]);
                    a[m][2] = __float_as_uint(s_hid[(r    ) * PHID + ac + gc + 4]);
                    a[m][3] = __float_as_uint(s_hid[(r + 8) * PHID + ac + gc + 4]);
                }
            }
            unsigned b0 = f2tf(wbuf[(kl + gc    ) * PW1B + c0 + gr]);
            unsigned b1 = f2tf(wbuf[(kl + gc + 4) * PW1B + c0 + gr]);
            mma_tf32(acc[t][0], a[0][0], a[0][1], a[0][2], a[0][3], b0, b1);
            mma_tf32(acc[t][1], a[1][0], a[1][1], a[1][2], a[1][3], b0, b1);
        }
    }
}

template<int HC, int NH, int MODE>   // MODE 0: store, 1: +=, 2: += then tf32-finalize
__device__ __forceinline__ void enc_epi(const float* __restrict__ bias, float* s_enc,
                                        int warp, int lane, int p, float acc[6][2][4]) {
    if (warp >= 12) return;
    const int gr = lane >> 2, gc = lane & 3;
    const int cw = warp * 48;
    #pragma unroll
    for (int t = 0; t < 6; t++) {
        int cb = cw + t * 8 + 2 * gc;
        int head = (HC == 576) ? 0 : ((HC == 64) ? (cb >> 6) : (cb >= 288 ? 1 : 0));
        int cc = cb - head * HC;
        float b0 = bias[(p * NH + head) * HC + cc];
        float b1 = bias[(p * NH + head) * HC + cc + 1];
        #pragma unroll
        for (int m = 0; m < 2; m++) {
            int r = m * 16 + gr;
            float v00 = lrelu(acc[t][m][0] + b0), v01 = lrelu(acc[t][m][1] + b1);
            float v10 = lrelu(acc[t][m][2] + b0), v11 = lrelu(acc[t][m][3] + b1);
            float* e0 = &s_enc[(r    ) * PENC + cb];
            float* e1 = &s_enc[(r + 8) * PENC + cb];
            if (MODE == 0)      { e0[0] = v00; e0[1] = v01; e1[0] = v10; e1[1] = v11; }
            else if (MODE == 1) { e0[0] += v00; e0[1] += v01; e1[0] += v10; e1[1] += v11; }
            else {
                e0[0] = tf32f(e0[0] + v00); e0[1] = tf32f(e0[1] + v01);
                e1[0] = tf32f(e1[0] + v10); e1[1] = tf32f(e1[1] + v11);
            }
        }
    }
}

// ---- pi-head GEMM stage: K-split across warp halves, cp.async ring-2 ----
// caller must have issued+committed chunks 0 and 1.
template<int KHALF, int PA, bool OUT_TF32>
__device__ __forceinline__ void pi_stage(const float* __restrict__ W0,
                                         const float* __restrict__ bias,
                                         const float* sA, float* wb, float* scr,
                                         float* outp, int outPitch,
                                         int tid, int warp, int lane) {
    constexpr int NCH = KHALF / 16;
    const int h = warp >> 3, nw = warp & 7, n0 = nw * 32, kb = h * KHALF;
    const int gr = lane >> 2, gc = lane & 3;

    float acc[4][2][4];
    #pragma unroll
    for (int j = 0; j < 4; j++)
        #pragma unroll
        for (int m = 0; m < 2; m++)
            #pragma unroll
            for (int u = 0; u < 4; u++) acc[j][m][u] = 0.f;

    for (int c = 0; c < NCH; c++) {
        cp_wait<1>();
        __syncthreads();
        const float* buf = wb + (h * 2 + (c & 1)) * (16 * PWB);
        #pragma unroll
        for (int ks = 0; ks < 2; ks++) {
            const int kg = kb + c * 16 + ks * 8;
            const int kl = ks * 8;
            unsigned a[2][4];
            #pragma unroll
            for (int m = 0; m < 2; m++) {
                int r = m * 16 + gr;
                a[m][0] = __float_as_uint(sA[(r    ) * PA + kg + gc    ]);
                a[m][1] = __float_as_uint(sA[(r + 8) * PA + kg + gc    ]);
                a[m][2] = __float_as_uint(sA[(r    ) * PA + kg + gc + 4]);
                a[m][3] = __float_as_uint(sA[(r + 8) * PA + kg + gc + 4]);
            }
            #pragma unroll
            for (int j = 0; j < 4; j++) {
                int n = n0 + j * 8 + gr;
                unsigned b0 = f2tf(buf[(kl + gc    ) * PWB + n]);
                unsigned b1 = f2tf(buf[(kl + gc + 4) * PWB + n]);
                mma_tf32(acc[j][0], a[0][0], a[0][1], a[0][2], a[0][3], b0, b1);
                mma_tf32(acc[j][1], a[1][0], a[1][1], a[1][2], a[1][3], b0, b1);
            }
        }
        __syncthreads();
        if (c + 2 < NCH) stage_pi(W0, wb, KHALF, c + 2, tid);
        CP_COMMIT();
    }

    // K-split reduction: half1 stores raw partials, half0 finalizes
    if (h == 1) {
        #pragma unroll
        for (int j = 0; j < 4; j++) {
            int cA = n0 + j * 8 + 2 * gc;
            #pragma unroll
            for (int m = 0; m < 2; m++) {
                int r = m * 16 + gr;
                scr[(r    ) * PSCR + cA] = acc[j][m][0]; scr[(r    ) * PSCR + cA + 1] = acc[j][m][1];
                scr[(r + 8) * PSCR + cA] = acc[j][m][2]; scr[(r + 8) * PSCR + cA + 1] = acc[j][m][3];
            }
        }
    }
    __syncthreads();
    if (h == 0) {
        #pragma unroll
        for (int j = 0; j < 4; j++) {
            int cA = n0 + j * 8 + 2 * gc;
            float b0 = bias[cA], b1 = bias[cA + 1];
            #pragma unroll
            for (int m = 0; m < 2; m++) {
                int r = m * 16 + gr;
                float v00 = lrelu(acc[j][m][0] + scr[(r    ) * PSCR + cA    ] + b0);
                float v01 = lrelu(acc[j][m][1] + scr[(r    ) * PSCR + cA + 1] + b1);
                float v10 = lrelu(acc[j][m][2] + scr[(r + 8) * PSCR + cA    ] + b0);
                float v11 = lrelu(acc[j][m][3] + scr[(r + 8) * PSCR + cA + 1] + b1);
                if (OUT_TF32) { v00 = tf32f(v00); v01 = tf32f(v01); v10 = tf32f(v10); v11 = tf32f(v11); }
                outp[(r    ) * outPitch + cA    ] = v00;
                outp[(r    ) * outPitch + cA + 1] = v01;
                outp[(r + 8) * outPitch + cA    ] = v10;
                outp[(r + 8) * outPitch + cA + 1] = v11;
            }
        }
    }
}

__global__ __launch_bounds__(THREADS, 1)
void mlpac_kernel(
    const float* __restrict__ obs,
    const float* __restrict__ prop_W1, const float* __restrict__ prop_b1,
    const float* __restrict__ prop_W2, const float* __restrict__ prop_b2,
    const float* __restrict__ ext_W1,  const float* __restrict__ ext_b1,
    const float* __restrict__ ext_W2,  const float* __restrict__ ext_b2,
    const float* __restrict__ opp_W1,  const float* __restrict__ opp_b1,
    const float* __restrict__ opp_W2,  const float* __restrict__ opp_b2,
    const float* __restrict__ pi_W1,   const float* __restrict__ pi_b1,
    const float* __restrict__ pi_W2,   const float* __restrict__ pi_b2,
    const float* __restrict__ pi_W3,   const float* __restrict__ pi_b3,
    float* __restrict__ out)
{
    extern __shared__ float sm[];
    float* s_hid = sm + HID_OFF;     // pitch PHID (tf32)
    float* s_enc = sm + ENC_OFF;     // pitch PENC
    float* s_h1  = sm + H1_OFF;      // pitch PH1 (tf32)
    float* s_wb  = sm + WB_OFF;
    float* s_obs = s_enc;            // obs staged in enc region (dead before 1b epilogues)
    float* s_w3  = sm + W3_STASH;

    const int tid  = threadIdx.x;
    const int warp = tid >> 5, lane = tid & 31;
    const int p    = blockIdx.y;
    const int b0   = blockIdx.x * TB;

    // ---------------- stage 0: obs via cp.async + prefetch 1b prop chunks ----------------
    for (int g = tid; g < TB * (OBSD / 4); g += THREADS) {
        int r = g / 12, q = g - r * 12;
        cpa16(cvta_s(s_obs + r * OBSD + q * 4),
              obs + ((size_t)(b0 + r) * NPLAYER + p) * OBSD + q * 4);
    }
    CP_COMMIT();                                                // C: obs
    stage_1b<64, 9>(prop_W2, s_wb, p, 0, tid);  CP_COMMIT();    // C: 1b chunk0
    stage_1b<64, 9>(prop_W2, s_wb + 16 * PW1B, p, 16, tid); CP_COMMIT(); // C: 1b chunk1
    cp_wait<2>();
    __syncthreads();

    // ---------------- stage 1a: branch hidden layers (tf32 stored) ----------------
    for (int i = tid; i < TB * 288; i += THREADS) {
        int r = i / 288, rest = i - r * 288, n = rest >> 5, j = rest & 31;
        const float* w = prop_W1 + ((p * 9 + n) * 2) * 32 + j;
        float h = s_obs[r * OBSD + 2 * n] * w[0]
                + s_obs[r * OBSD + 2 * n + 1] * w[32]
                + prop_b1[(p * 9 + n) * 32 + j];
        s_hid[r * PHID + n * 32 + j] = tf32f(lrelu(h));
    }
    for (int i = tid; i < TB * 64; i += THREADS) {
        int r = i >> 6, rest = i & 63, n = rest >> 5, j = rest & 31;
        const float* w = ext_W1 + ((p * 2 + n) * 6) * 32 + j;
        float h = ext_b1[(p * 2 + n) * 32 + j];
        #pragma unroll
        for (int q = 0; q < 6; q++) h += s_obs[r * OBSD + 18 + n * 6 + q] * w[q * 32];
        s_hid[r * PHID + 288 + n * 32 + j] = tf32f(lrelu(h));
    }
    for (int i = tid; i < TB * 32; i += THREADS) {
        int r = i >> 5, j = i & 31;
        const float* w = opp_W1 + (p * 18) * 32 + j;
        float h = opp_b1[p * 32 + j];
        #pragma unroll
        for (int q = 0; q < 18; q++) h += s_obs[r * OBSD + 30 + q] * w[q * 32];
        s_hid[r * PHID + 352 + j] = tf32f(lrelu(h));
    }
    // (no sync needed: 1b iter0's cp_wait + sync covers hid visibility)

    // ---------------- stage 1b: enc = sum of lrelu(branch @ W2 + b2), pipelined ----------------
    {
        int cidx = 0;
        #pragma unroll
        for (int pp = 0; pp < 3; pp++) {
            float acc[6][2][4];
            #pragma unroll
            for (int t = 0; t < 6; t++)
                #pragma unroll
                for (int m = 0; m < 2; m++)
                    #pragma unroll
                    for (int u = 0; u < 4; u++) acc[t][m][u] = 0.f;

            #pragma unroll
            for (int kh = 0; kh < 2; kh++, cidx++) {
                cp_wait<1>();
                __syncthreads();
                const float* buf = s_wb + (cidx & 1) * (16 * PW1B);
                if (pp == 0)      enc_mma<64, 9, 0  >(s_hid, buf, warp, lane, kh, acc);
                else if (pp == 1) enc_mma<288, 2, 288>(s_hid, buf, warp, lane, kh, acc);
                else              enc_mma<576, 1, 352>(s_hid, buf, warp, lane, kh, acc);
                __syncthreads();
                if (cidx + 2 < 6) {
                    float* dst = s_wb + (cidx & 1) * (16 * PW1B);
                    int k0 = (cidx & 1) ? 16 : 0;    // chunk cidx+2 has same parity as cidx
                    int np = (cidx + 2) >> 1;
                    if (np == 1)      stage_1b<288, 2>(ext_W2, dst, p, k0, tid);
                    else              stage_1b<576, 1>(opp_W2, dst, p, k0, tid);
                }
                CP_COMMIT();
            }
            if (pp == 0)      enc_epi<64, 9, 0>(prop_b2, s_enc, warp, lane, p, acc);
            else if (pp == 1) enc_epi<288, 2, 1>(ext_b2, s_enc, warp, lane, p, acc);
            else              enc_epi<576, 1, 2>(opp_b2, s_enc, warp, lane, p, acc);
        }
    }

    // ---------------- stage 2: h1 = lrelu(enc @ pi_W1 + b1) ----------------
    const float* W1p = pi_W1 + (size_t)p * 576 * 256;
    stage_pi(W1p, s_wb, 288, 0, tid); CP_COMMIT();
    stage_pi(W1p, s_wb, 288, 1, tid); CP_COMMIT();
    pi_stage<288, PENC, true>(W1p, pi_b1 + p * 256, s_enc, s_wb,
                              s_hid /*scratch*/, s_h1, PH1, tid, warp, lane);

    // ---------------- stage 3: h2 = lrelu(h1 @ pi_W2 + b2) ----------------
    const float* W2p = pi_W2 + (size_t)p * 256 * 256;
    stage_pi(W2p, s_wb, 128, 0, tid);
    if (tid < 192) cpa16(cvta_s(s_w3 + tid * 4), pi_W3 + (size_t)p * 768 + tid * 4);
    CP_COMMIT();
    stage_pi(W2p, s_wb, 128, 1, tid); CP_COMMIT();
    pi_stage<128, PH1, false>(W2p, pi_b2 + p * 256, s_h1, s_wb,
                              s_enc /*scratch*/, s_hid /*h2, pitch 256*/, 256,
                              tid, warp, lane);

    if (tid < 3) s_w3[768 + tid] = pi_b3[p * 3 + tid];
    __syncthreads();

    // ---------------- stage 4: out = tanh(h2 @ pi_W3 + b3) ----------------
    if (tid < TB * 3) {
        int r = tid / 3, a = tid % 3;
        float s = s_w3[768 + a];
        #pragma unroll 8
        for (int i = 0; i < 256; i++) s += s_hid[r * 256 + i] * s_w3[i * 3 + a];
        out[((size_t)(b0 + r) * NPLAYER + p) * 3 + a] = tanhf(s);
    }
}

extern "C" void kernel_launch(void* const* d_in, const int* in_sizes, int n_in,
                              void* d_out, int out_size)
{
    (void)in_sizes; (void)n_in; (void)out_size;
    const float* obs     = (const float*)d_in[0];
    const float* prop_W1 = (const float*)d_in[1];
    const float* prop_b1 = (const float*)d_in[2];
    const float* prop_W2 = (const float*)d_in[3];
    const float* prop_b2 = (const float*)d_in[4];
    const float* ext_W1  = (const float*)d_in[5];
    const float* ext_b1  = (const float*)d_in[6];
    const float* ext_W2  = (const float*)d_in[7];
    const float* ext_b2  = (const float*)d_in[8];
    const float* opp_W1  = (const float*)d_in[9];
    const float* opp_b1  = (const float*)d_in[10];
    const float* opp_W2  = (const float*)d_in[11];
    const float* opp_b2  = (const float*)d_in[12];
    const float* pi_W1   = (const float*)d_in[13];
    const float* pi_b1   = (const float*)d_in[14];
    const float* pi_W2   = (const float*)d_in[15];
    const float* pi_b2   = (const float*)d_in[16];
    const float* pi_W3   = (const float*)d_in[17];
    const float* pi_b3   = (const float*)d_in[18];
    float* out = (float*)d_out;

    const int smem_bytes = SMEM_FLOATS * sizeof(float);
    cudaFuncSetAttribute(mlpac_kernel, cudaFuncAttributeMaxDynamicSharedMemorySize, smem_bytes);

    dim3 grid(BATCH / TB, NPLAYER);
    mlpac_kernel<<<grid, THREADS, smem_bytes>>>(
        obs, prop_W1, prop_b1, prop_W2, prop_b2,
        ext_W1, ext_b1, ext_W2, ext_b2,
        opp_W1, opp_b1, opp_W2, opp_b2,
        pi_W1, pi_b1, pi_W2, pi_b2, pi_W3, pi_b3, out);
}

// round 6
// speedup vs baseline: 1.6459x; 1.6459x over previous
#include <cuda_runtime.h>

#define BATCH   65536
#define NPLAYER 3
#define OBSD    48
#define TB      32
#define THREADS 512

// pitches (floats) — conflict-free for mma fragment patterns
#define PHID 388
#define PENC 580
#define PH1  260
#define PSCR 260

// smem float offsets
#define HID_OFF 0                      // 12416: hid(388) -> stage2 scratch(260) -> h2(256)
#define ENC_OFF 12416                  // 18560: obs -> enc(580) -> stage3 scratch(260)
#define H1_OFF  (ENC_OFF + 18560)      // 8320: h1(260) -> stage4 partials
#define W3_OFF  (H1_OFF + 8320)        // 772: dedicated w3(768) + b3(3) — NO overlap
#define SMEM_FLOATS (W3_OFF + 772)     // 40068 floats = 160272 B

__device__ __forceinline__ float lrelu(float x) { return fmaxf(x, 0.01f * x); }

__device__ __forceinline__ unsigned f2tf(float x) {
    unsigned r;
    asm("cvt.rna.tf32.f32 %0, %1;" : "=r"(r) : "f"(x));
    return r;
}
__device__ __forceinline__ float tf32f(float x) { return __uint_as_float(f2tf(x)); }

__device__ __forceinline__ void mma_tf32(float d[4], unsigned a0, unsigned a1,
                                         unsigned a2, unsigned a3,
                                         unsigned b0, unsigned b1) {
    asm volatile(
        "mma.sync.aligned.m16n8k8.row.col.f32.tf32.tf32.f32 "
        "{%0,%1,%2,%3}, {%4,%5,%6,%7}, {%8,%9}, {%0,%1,%2,%3};"
        : "+f"(d[0]), "+f"(d[1]), "+f"(d[2]), "+f"(d[3])
        : "r"(a0), "r"(a1), "r"(a2), "r"(a3), "r"(b0), "r"(b1));
}

// ---------------- stage-1b pass: B straight from global, no syncs ----------------
// MODE 0: store, 1: accumulate, 2: accumulate + tf32-finalize
template<int HC, int NH, int ABASE, int MODE>
__device__ __forceinline__ void enc_pass(const float* __restrict__ W,
                                         const float* __restrict__ bias,
                                         const float* s_hid, float* s_enc,
                                         int warp, int lane, int p) {
    if (warp >= 12) return;
    const int gr = lane >> 2, gc = lane & 3;
    const int cw = warp * 48;

    const float* wt[6];
    int headA[6];
    #pragma unroll
    for (int t = 0; t < 6; t++) {
        int c0 = cw + t * 8;
        int head = (HC == 576) ? 0 : ((HC == 64) ? (c0 >> 6) : (c0 >= 288 ? 1 : 0));
        headA[t] = head;
        wt[t] = W + ((size_t)(p * NH + head) * 32 + gc) * HC + (c0 - head * HC) + gr;
    }

    float acc[6][2][4];
    #pragma unroll
    for (int t = 0; t < 6; t++)
        #pragma unroll
        for (int m = 0; m < 2; m++)
            #pragma unroll
            for (int u = 0; u < 4; u++) acc[t][m][u] = 0.f;

    #pragma unroll
    for (int k8 = 0; k8 < 4; k8++) {
        float bf[6][2];
        #pragma unroll
        for (int t = 0; t < 6; t++) {
            bf[t][0] = wt[t][(k8 * 8    ) * HC];
            bf[t][1] = wt[t][(k8 * 8 + 4) * HC];
        }
        int cur = -1;
        unsigned a[2][4];
        #pragma unroll
        for (int t = 0; t < 6; t++) {
            if (headA[t] != cur) {
                cur = headA[t];
                int ac = ABASE + cur * 32 + k8 * 8 + gc;
                #pragma unroll
                for (int m = 0; m < 2; m++) {
                    int r = m * 16 + gr;
                    a[m][0] = __float_as_uint(s_hid[(r    ) * PHID + ac    ]);
                    a[m][1] = __float_as_uint(s_hid[(r + 8) * PHID + ac    ]);
                    a[m][2] = __float_as_uint(s_hid[(r    ) * PHID + ac + 4]);
                    a[m][3] = __float_as_uint(s_hid[(r + 8) * PHID + ac + 4]);
                }
            }
            unsigned b0 = f2tf(bf[t][0]), b1 = f2tf(bf[t][1]);
            mma_tf32(acc[t][0], a[0][0], a[0][1], a[0][2], a[0][3], b0, b1);
            mma_tf32(acc[t][1], a[1][0], a[1][1], a[1][2], a[1][3], b0, b1);
        }
    }

    // epilogue: warp-private columns -> no cross-warp hazard
    #pragma unroll
    for (int t = 0; t < 6; t++) {
        int cb = cw + t * 8 + 2 * gc;
        int head = headA[t];
        int cc = cb - head * HC;
        float b0 = bias[(p * NH + head) * HC + cc];
        float b1 = bias[(p * NH + head) * HC + cc + 1];
        #pragma unroll
        for (int m = 0; m < 2; m++) {
            int r = m * 16 + gr;
            float v00 = lrelu(acc[t][m][0] + b0), v01 = lrelu(acc[t][m][1] + b1);
            float v10 = lrelu(acc[t][m][2] + b0), v11 = lrelu(acc[t][m][3] + b1);
            float* e0 = &s_enc[(r    ) * PENC + cb];
            float* e1 = &s_enc[(r + 8) * PENC + cb];
            if (MODE == 0)      { e0[0] = v00; e0[1] = v01; e1[0] = v10; e1[1] = v11; }
            else if (MODE == 1) { e0[0] += v00; e0[1] += v01; e1[0] += v10; e1[1] += v11; }
            else {
                e0[0] = tf32f(e0[0] + v00); e0[1] = tf32f(e0[1] + v01);
                e1[0] = tf32f(e1[0] + v10); e1[1] = tf32f(e1[1] + v11);
            }
        }
    }
}

// ---------------- pi-head GEMM: K-split halves, B from global, no inner syncs ----------------
template<int KHALF, int PA, bool OUT_TF32>
__device__ __forceinline__ void pi_stage(const float* __restrict__ W,
                                         const float* __restrict__ bias,
                                         const float* sA, float* scr,
                                         float* outp, int outPitch,
                                         int warp, int lane) {
    const int h = warp >> 3, nw = warp & 7, n0 = nw * 32;
    const int gr = lane >> 2, gc = lane & 3;
    const float* W0 = W + ((size_t)(h * KHALF) + gc) * 256 + n0 + gr;
    const int kbase = h * KHALF + gc;

    float acc[4][2][4];
    #pragma unroll
    for (int j = 0; j < 4; j++)
        #pragma unroll
        for (int m = 0; m < 2; m++)
            #pragma unroll
            for (int u = 0; u < 4; u++) acc[j][m][u] = 0.f;

    #pragma unroll 2
    for (int c = 0; c < KHALF / 8; c++) {
        const float* wp = W0 + (size_t)c * 8 * 256;
        float bf[8];
        #pragma unroll
        for (int j = 0; j < 4; j++) {
            bf[2 * j    ] = wp[j * 8];
            bf[2 * j + 1] = wp[1024 + j * 8];   // +4 k-rows
        }
        const int kg = kbase + c * 8;
        unsigned a[2][4];
        #pragma unroll
        for (int m = 0; m < 2; m++) {
            int r = m * 16 + gr;
            a[m][0] = __float_as_uint(sA[(r    ) * PA + kg    ]);
            a[m][1] = __float_as_uint(sA[(r + 8) * PA + kg    ]);
            a[m][2] = __float_as_uint(sA[(r    ) * PA + kg + 4]);
            a[m][3] = __float_as_uint(sA[(r + 8) * PA + kg + 4]);
        }
        #pragma unroll
        for (int j = 0; j < 4; j++) {
            unsigned b0 = f2tf(bf[2 * j]), b1 = f2tf(bf[2 * j + 1]);
            mma_tf32(acc[j][0], a[0][0], a[0][1], a[0][2], a[0][3], b0, b1);
            mma_tf32(acc[j][1], a[1][0], a[1][1], a[1][2], a[1][3], b0, b1);
        }
    }

    // K-split reduction
    if (h == 1) {
        #pragma unroll
        for (int j = 0; j < 4; j++) {
            int cA = n0 + j * 8 + 2 * gc;
            #pragma unroll
            for (int m = 0; m < 2; m++) {
                int r = m * 16 + gr;
                scr[(r    ) * PSCR + cA] = acc[j][m][0]; scr[(r    ) * PSCR + cA + 1] = acc[j][m][1];
                scr[(r + 8) * PSCR + cA] = acc[j][m][2]; scr[(r + 8) * PSCR + cA + 1] = acc[j][m][3];
            }
        }
    }
    __syncthreads();
    if (h == 0) {
        #pragma unroll
        for (int j = 0; j < 4; j++) {
            int cA = n0 + j * 8 + 2 * gc;
            float b0 = bias[cA], b1 = bias[cA + 1];
            #pragma unroll
            for (int m = 0; m < 2; m++) {
                int r = m * 16 + gr;
                float v00 = lrelu(acc[j][m][0] + scr[(r    ) * PSCR + cA    ] + b0);
                float v01 = lrelu(acc[j][m][1] + scr[(r    ) * PSCR + cA + 1] + b1);
                float v10 = lrelu(acc[j][m][2] + scr[(r + 8) * PSCR + cA    ] + b0);
                float v11 = lrelu(acc[j][m][3] + scr[(r + 8) * PSCR + cA + 1] + b1);
                if (OUT_TF32) { v00 = tf32f(v00); v01 = tf32f(v01); v10 = tf32f(v10); v11 = tf32f(v11); }
                outp[(r    ) * outPitch + cA    ] = v00;
                outp[(r    ) * outPitch + cA + 1] = v01;
                outp[(r + 8) * outPitch + cA    ] = v10;
                outp[(r + 8) * outPitch + cA + 1] = v11;
            }
        }
    }
}

__global__ __launch_bounds__(THREADS, 1)
void mlpac_kernel(
    const float* __restrict__ obs,
    const float* __restrict__ prop_W1, const float* __restrict__ prop_b1,
    const float* __restrict__ prop_W2, const float* __restrict__ prop_b2,
    const float* __restrict__ ext_W1,  const float* __restrict__ ext_b1,
    const float* __restrict__ ext_W2,  const float* __restrict__ ext_b2,
    const float* __restrict__ opp_W1,  const float* __restrict__ opp_b1,
    const float* __restrict__ opp_W2,  const float* __restrict__ opp_b2,
    const float* __restrict__ pi_W1,   const float* __restrict__ pi_b1,
    const float* __restrict__ pi_W2,   const float* __restrict__ pi_b2,
    const float* __restrict__ pi_W3,   const float* __restrict__ pi_b3,
    float* __restrict__ out)
{
    extern __shared__ float sm[];
    float* s_hid  = sm + HID_OFF;   // pitch PHID (tf32)
    float* s_enc  = sm + ENC_OFF;   // pitch PENC
    float* s_h1   = sm + H1_OFF;    // pitch PH1 (tf32)
    float* s_obs  = s_enc;          // obs staged in enc region (dead before 1b epilogue)
    float* s_w3   = sm + W3_OFF;    // dedicated region: 768 w3 + 3 b3
    float* s_part = sm + H1_OFF;    // stage4 partials (h1 dead by then)

    const int tid  = threadIdx.x;
    const int warp = tid >> 5, lane = tid & 31;
    const int p    = blockIdx.y;
    const int b0   = blockIdx.x * TB;

    // ---------------- stage 0: obs tile + w3/b3 stash ----------------
    for (int g = tid; g < TB * (OBSD / 4); g += THREADS) {
        int r = g / 12, q = g - r * 12;
        *(float4*)&s_obs[r * OBSD + q * 4] =
            *(const float4*)&obs[((size_t)(b0 + r) * NPLAYER + p) * OBSD + q * 4];
    }
    for (int g = tid; g < 768; g += THREADS) s_w3[g] = pi_W3[(size_t)p * 768 + g];
    if (tid < 3) s_w3[768 + tid] = pi_b3[p * 3 + tid];
    __syncthreads();

    // ---------------- stage 1a: branch hidden layers (tf32 stored) ----------------
    for (int i = tid; i < TB * 288; i += THREADS) {
        int r = i / 288, rest = i - r * 288, n = rest >> 5, j = rest & 31;
        const float* w = prop_W1 + ((p * 9 + n) * 2) * 32 + j;
        float h = s_obs[r * OBSD + 2 * n] * w[0]
                + s_obs[r * OBSD + 2 * n + 1] * w[32]
                + prop_b1[(p * 9 + n) * 32 + j];
        s_hid[r * PHID + n * 32 + j] = tf32f(lrelu(h));
    }
    for (int i = tid; i < TB * 64; i += THREADS) {
        int r = i >> 6, rest = i & 63, n = rest >> 5, j = rest & 31;
        const float* w = ext_W1 + ((p * 2 + n) * 6) * 32 + j;
        float h = ext_b1[(p * 2 + n) * 32 + j];
        #pragma unroll
        for (int q = 0; q < 6; q++) h += s_obs[r * OBSD + 18 + n * 6 + q] * w[q * 32];
        s_hid[r * PHID + 288 + n * 32 + j] = tf32f(lrelu(h));
    }
    for (int i = tid; i < TB * 32; i += THREADS) {
        int r = i >> 5, j = i & 31;
        const float* w = opp_W1 + (p * 18) * 32 + j;
        float h = opp_b1[p * 32 + j];
        #pragma unroll
        for (int q = 0; q < 18; q++) h += s_obs[r * OBSD + 30 + q] * w[q * 32];
        s_hid[r * PHID + 352 + j] = tf32f(lrelu(h));
    }
    __syncthreads();   // hid visible; obs dead

    // ---------------- stage 1b: enc = sum of branch-2 layers (no internal syncs) ----
    enc_pass<64,  9, 0,   0>(prop_W2, prop_b2, s_hid, s_enc, warp, lane, p);
    enc_pass<288, 2, 288, 1>(ext_W2,  ext_b2,  s_hid, s_enc, warp, lane, p);
    enc_pass<576, 1, 352, 2>(opp_W2,  opp_b2,  s_hid, s_enc, warp, lane, p);
    __syncthreads();   // enc complete; hid reads complete

    // ---------------- stage 2: h1 = lrelu(enc @ pi_W1 + b1) ----------------
    pi_stage<288, PENC, true>(pi_W1 + (size_t)p * 576 * 256, pi_b1 + p * 256,
                              s_enc, s_hid /*scratch*/, s_h1, PH1, warp, lane);
    __syncthreads();   // h1 visible

    // ---------------- stage 3: h2 = lrelu(h1 @ pi_W2 + b2) ----------------
    pi_stage<128, PH1, false>(pi_W2 + (size_t)p * 256 * 256, pi_b2 + p * 256,
                              s_h1, s_enc /*scratch*/, s_hid /*h2*/, 256, warp, lane);
    __syncthreads();   // h2 visible; h1 dead -> partials region

    // ---------------- stage 4: out = tanh(h2 @ pi_W3 + b3), 4-way split ----------------
    if (tid < 384) {
        int q = tid & 3, a = (tid >> 2) % 3, r = tid / 12;
        float s = 0.f;
        const float* h2 = &s_hid[r * 256 + q * 64];
        const float* w3 = &s_w3[q * 64 * 3 + a];
        #pragma unroll 16
        for (int i = 0; i < 64; i++) s += h2[i] * w3[i * 3];
        s_part[tid] = s;
    }
    __syncthreads();
    if (tid < TB * 3) {
        int r = tid / 3, a = tid % 3;
        int base = (r * 3 + a) * 4;
        float s = s_w3[768 + a] + s_part[base] + s_part[base + 1]
                + s_part[base + 2] + s_part[base + 3];
        out[((size_t)(b0 + r) * NPLAYER + p) * 3 + a] = tanhf(s);
    }
}

extern "C" void kernel_launch(void* const* d_in, const int* in_sizes, int n_in,
                              void* d_out, int out_size)
{
    (void)in_sizes; (void)n_in; (void)out_size;
    const float* obs     = (const float*)d_in[0];
    const float* prop_W1 = (const float*)d_in[1];
    const float* prop_b1 = (const float*)d_in[2];
    const float* prop_W2 = (const float*)d_in[3];
    const float* prop_b2 = (const float*)d_in[4];
    const float* ext_W1  = (const float*)d_in[5];
    const float* ext_b1  = (const float*)d_in[6];
    const float* ext_W2  = (const float*)d_in[7];
    const float* ext_b2  = (const float*)d_in[8];
    const float* opp_W1  = (const float*)d_in[9];
    const float* opp_b1  = (const float*)d_in[10];
    const float* opp_W2  = (const float*)d_in[11];
    const float* opp_b2  = (const float*)d_in[12];
    const float* pi_W1   = (const float*)d_in[13];
    const float* pi_b1   = (const float*)d_in[14];
    const float* pi_W2   = (const float*)d_in[15];
    const float* pi_b2   = (const float*)d_in[16];
    const float* pi_W3   = (const float*)d_in[17];
    const float* pi_b3   = (const float*)d_in[18];
    float* out = (float*)d_out;

    const int smem_bytes = SMEM_FLOATS * sizeof(float);
    cudaFuncSetAttribute(mlpac_kernel, cudaFuncAttributeMaxDynamicSharedMemorySize, smem_bytes);

    dim3 grid(BATCH / TB, NPLAYER);
    mlpac_kernel<<<grid, THREADS, smem_bytes>>>(
        obs, prop_W1, prop_b1, prop_W2, prop_b2,
        ext_W1, ext_b1, ext_W2, ext_b2,
        opp_W1, opp_b1, opp_W2, opp_b2,
        pi_W1, pi_b1, pi_W2, pi_b2, pi_W3, pi_b3, out);
}